// round 8
// baseline (speedup 1.0000x reference)
#include <cuda_runtime.h>

// inputs [4,64,512,512] f32, targets [4,512,512] int32, group_ids [64] i32 -> scalar f32.
#define B_     4
#define C_     64
#define HW_    (512 * 512)          // 262144
#define NPIX_  (B_ * HW_)           // 1048576
#define BLOCK_ 256
#define PPT_   4                    // pixels per thread (float4)
#define NBLK_  (NPIX_ / (BLOCK_ * PPT_))   // 1024
#define IGNORE_IDX 255

__device__ float g_psum[NBLK_];
__device__ float g_pcnt[NBLK_];
__device__ unsigned int g_ctr;      // zero-initialized; self-resets each run

__global__ void __launch_bounds__(BLOCK_)
uni_ce2d_fused(const float* __restrict__ inp,
               const int* __restrict__ tgt,
               const int* __restrict__ gid,
               float* __restrict__ out)
{
    __shared__ int sgid[C_];
    if (threadIdx.x < C_) sgid[threadIdx.x] = gid[threadIdx.x];
    __syncthreads();

    // Each thread owns 4 consecutive pixels.
    const int q = (blockIdx.x * BLOCK_ + threadIdx.x) * PPT_;  // base pixel
    const int b = q >> 18;                                     // q / HW_
    const int p = q & (HW_ - 1);                               // q % HW_ (4-aligned)

    const float* base = inp + (size_t)b * C_ * HW_ + p;

    const int4 t4 = *(const int4*)(tgt + q);
    const int t[PPT_] = { t4.x, t4.y, t4.z, t4.w };
    bool valid[PPT_];
    int  tt[PPT_];
#pragma unroll
    for (int j = 0; j < PPT_; ++j) {
        valid[j] = (t[j] != IGNORE_IDX);
        tt[j]    = valid[j] ? t[j] : 0;
    }

    // No max shift needed: any shift cancels in log(sgrp) - log(stot),
    // and inputs are O(1) so expf is safe unshifted.
    float stot[PPT_] = {0.f, 0.f, 0.f, 0.f};
    float sgrp[PPT_] = {0.f, 0.f, 0.f, 0.f};

#pragma unroll
    for (int c = 0; c < C_; ++c) {
        const float4 v = *(const float4*)(base + (size_t)c * HW_);
        const int g = sgid[c];
        float e0 = __expf(v.x), e1 = __expf(v.y), e2 = __expf(v.z), e3 = __expf(v.w);
        stot[0] += e0; stot[1] += e1; stot[2] += e2; stot[3] += e3;
        sgrp[0] += (g == tt[0]) ? e0 : 0.f;
        sgrp[1] += (g == tt[1]) ? e1 : 0.f;
        sgrp[2] += (g == tt[2]) ? e2 : 0.f;
        sgrp[3] += (g == tt[3]) ? e3 : 0.f;
    }

    float contrib = 0.f, cnt = 0.f;
#pragma unroll
    for (int j = 0; j < PPT_; ++j) {
        float lp = __logf(sgrp[j]) - __logf(stot[j]);
        contrib += valid[j] ? -lp : 0.f;
        cnt     += valid[j] ? 1.f : 0.f;
    }

    // Warp reduce
#pragma unroll
    for (int o = 16; o > 0; o >>= 1) {
        contrib += __shfl_down_sync(0xFFFFFFFFu, contrib, o);
        cnt     += __shfl_down_sync(0xFFFFFFFFu, cnt, o);
    }

    __shared__ float ssum[BLOCK_ / 32];
    __shared__ float scnt[BLOCK_ / 32];
    __shared__ bool  s_last;
    const int lane = threadIdx.x & 31;
    const int wid  = threadIdx.x >> 5;
    if (lane == 0) { ssum[wid] = contrib; scnt[wid] = cnt; }
    __syncthreads();

    if (wid == 0) {
        float s = (lane < BLOCK_ / 32) ? ssum[lane] : 0.f;
        float c = (lane < BLOCK_ / 32) ? scnt[lane] : 0.f;
#pragma unroll
        for (int o = 4; o > 0; o >>= 1) {
            s += __shfl_down_sync(0xFFFFFFFFu, s, o);
            c += __shfl_down_sync(0xFFFFFFFFu, c, o);
        }
        if (lane == 0) {
            g_psum[blockIdx.x] = s;
            g_pcnt[blockIdx.x] = c;
            __threadfence();
            unsigned prev = atomicAdd(&g_ctr, 1u);
            s_last = (prev == (unsigned)(gridDim.x - 1));
        }
    }
    __syncthreads();

    // Last block performs the final (deterministic, fixed-order) reduction.
    if (s_last) {
        double s = 0.0, c = 0.0;
        for (int i = threadIdx.x; i < NBLK_; i += BLOCK_) {
            s += (double)g_psum[i];
            c += (double)g_pcnt[i];
        }
#pragma unroll
        for (int o = 16; o > 0; o >>= 1) {
            s += __shfl_down_sync(0xFFFFFFFFu, s, o);
            c += __shfl_down_sync(0xFFFFFFFFu, c, o);
        }
        __shared__ double ds[BLOCK_ / 32], dc[BLOCK_ / 32];
        if (lane == 0) { ds[wid] = s; dc[wid] = c; }
        __syncthreads();
        if (wid == 0) {
            double ss = (lane < BLOCK_ / 32) ? ds[lane] : 0.0;
            double cc = (lane < BLOCK_ / 32) ? dc[lane] : 0.0;
#pragma unroll
            for (int o = 4; o > 0; o >>= 1) {
                ss += __shfl_down_sync(0xFFFFFFFFu, ss, o);
                cc += __shfl_down_sync(0xFFFFFFFFu, cc, o);
            }
            if (lane == 0) {
                double denom = (cc > 1.0) ? cc : 1.0;
                out[0] = (float)(ss / denom);
                g_ctr = 0;          // reset for next graph replay
            }
        }
    }
}

extern "C" void kernel_launch(void* const* d_in, const int* in_sizes, int n_in,
                              void* d_out, int out_size)
{
    const float* inp = (const float*)d_in[0];
    const int*   tgt = (const int*)d_in[1];
    const int*   gid = (const int*)d_in[2];
    float*       out = (float*)d_out;

    uni_ce2d_fused<<<NBLK_, BLOCK_>>>(inp, tgt, gid, out);
}

// round 12
// speedup vs baseline: 1.0373x; 1.0373x over previous
#include <cuda_runtime.h>

// inputs [4,64,512,512] f32, targets [4,512,512] int32, group_ids [64] i32 -> scalar f32.
#define B_     4
#define C_     64
#define HW_    (512 * 512)          // 262144
#define NPIX_  (B_ * HW_)           // 1048576
#define BLOCK_ 256
#define NBLK_  (NPIX_ / BLOCK_)     // 4096
#define IGNORE_IDX 255

__device__ float g_psum[NBLK_];
__device__ float g_pcnt[NBLK_];
__device__ unsigned int g_ctr;      // zero-init; self-resets each replay

__global__ void __launch_bounds__(BLOCK_)
uni_ce2d_fused(const float* __restrict__ inp,
               const int* __restrict__ tgt,
               const int* __restrict__ gid,
               float* __restrict__ out)
{
    __shared__ int sgid[C_];
    if (threadIdx.x < C_) sgid[threadIdx.x] = gid[threadIdx.x];
    __syncthreads();

    const int i = blockIdx.x * BLOCK_ + threadIdx.x;   // pixel index
    const int b = i >> 18;                              // i / HW_
    const int p = i & (HW_ - 1);                        // i % HW_

    const float* base = inp + (size_t)b * C_ * HW_ + p;

    // Front-batch all 64 channel loads -> maximal MLP (this is what makes
    // the kernel bandwidth-bound instead of latency-bound).
    float v[C_];
#pragma unroll
    for (int c = 0; c < C_; ++c)
        v[c] = base[(size_t)c * HW_];

    const int t = tgt[i];
    const bool valid = (t != IGNORE_IDX);
    const int tt = valid ? t : 0;

    // No max shift: any shift cancels in log(sgrp)-log(stot); inputs are O(1).
    float stot = 0.0f, sgrp = 0.0f;
#pragma unroll
    for (int c = 0; c < C_; ++c) {
        float e = __expf(v[c]);
        stot += e;
        sgrp += (sgid[c] == tt) ? e : 0.0f;
    }

    float lp = __logf(sgrp) - __logf(stot);
    float contrib = valid ? -lp : 0.0f;
    float cnt = valid ? 1.0f : 0.0f;

    // Warp reduce
#pragma unroll
    for (int o = 16; o > 0; o >>= 1) {
        contrib += __shfl_down_sync(0xFFFFFFFFu, contrib, o);
        cnt     += __shfl_down_sync(0xFFFFFFFFu, cnt, o);
    }

    __shared__ float ssum[BLOCK_ / 32];
    __shared__ float scnt[BLOCK_ / 32];
    __shared__ bool  s_last;
    const int lane = threadIdx.x & 31;
    const int wid  = threadIdx.x >> 5;
    if (lane == 0) { ssum[wid] = contrib; scnt[wid] = cnt; }
    __syncthreads();

    if (wid == 0) {
        float s = (lane < BLOCK_ / 32) ? ssum[lane] : 0.0f;
        float c = (lane < BLOCK_ / 32) ? scnt[lane] : 0.0f;
#pragma unroll
        for (int o = 4; o > 0; o >>= 1) {
            s += __shfl_down_sync(0xFFFFFFFFu, s, o);
            c += __shfl_down_sync(0xFFFFFFFFu, c, o);
        }
        if (lane == 0) {
            g_psum[blockIdx.x] = s;
            g_pcnt[blockIdx.x] = c;
            __threadfence();
            unsigned prev = atomicAdd(&g_ctr, 1u);
            s_last = (prev == (unsigned)(gridDim.x - 1));
        }
    }
    __syncthreads();

    // Last arriving block does the final fixed-order reduction (deterministic).
    if (s_last) {
        double s = 0.0, c = 0.0;
        for (int k = threadIdx.x; k < NBLK_; k += BLOCK_) {
            s += (double)g_psum[k];
            c += (double)g_pcnt[k];
        }
#pragma unroll
        for (int o = 16; o > 0; o >>= 1) {
            s += __shfl_down_sync(0xFFFFFFFFu, s, o);
            c += __shfl_down_sync(0xFFFFFFFFu, c, o);
        }
        __shared__ double ds[BLOCK_ / 32], dc[BLOCK_ / 32];
        if (lane == 0) { ds[wid] = s; dc[wid] = c; }
        __syncthreads();
        if (wid == 0) {
            double ss = (lane < BLOCK_ / 32) ? ds[lane] : 0.0;
            double cc = (lane < BLOCK_ / 32) ? dc[lane] : 0.0;
#pragma unroll
            for (int o = 4; o > 0; o >>= 1) {
                ss += __shfl_down_sync(0xFFFFFFFFu, ss, o);
                cc += __shfl_down_sync(0xFFFFFFFFu, cc, o);
            }
            if (lane == 0) {
                double denom = (cc > 1.0) ? cc : 1.0;
                out[0] = (float)(ss / denom);
                g_ctr = 0;          // reset for next graph replay
            }
        }
    }
}

extern "C" void kernel_launch(void* const* d_in, const int* in_sizes, int n_in,
                              void* d_out, int out_size)
{
    const float* inp = (const float*)d_in[0];
    const int*   tgt = (const int*)d_in[1];
    const int*   gid = (const int*)d_in[2];
    float*       out = (float*)d_out;

    uni_ce2d_fused<<<NBLK_, BLOCK_>>>(inp, tgt, gid, out);
}